// round 6
// baseline (speedup 1.0000x reference)
#include <cuda_runtime.h>
#include <cuda_bf16.h>
#include <cstdint>
#include <cstddef>

#define NE 50000

typedef unsigned long long ull;

// ---------------- fp32 scratch (GEMM outputs only) ----------------------------
__device__ float g_pre[NE * 128];
__device__ float g_rad[NE * 3072];
__device__ float g_c0 [NE * 1152];
__device__ float g_c1 [NE * 2048];   // (2E, 1024)
__device__ float g_c2 [NE * 1536];   // (2E, 768)
__device__ float g_d0 [NE * 640];
__device__ float g_d1 [NE * 2048];   // (2E, 1024)
__device__ float g_d2 [NE * 1536];   // (2E, 768)

// ---------------- int8 quantized activations (hi, lo) -------------------------
__device__ int8_t q_xe1[NE * 128],  q_xe0[NE * 128];
__device__ int8_t q_h1 [NE * 128],  q_h0 [NE * 128];
__device__ int8_t q_x01[NE * 1280], q_x00[NE * 1280];
__device__ int8_t q_x11[NE * 2048], q_x10[NE * 2048];
__device__ int8_t q_x21[NE * 1536], q_x20[NE * 1536];
__device__ int8_t q_u01[NE * 640],  q_u00[NE * 640];
__device__ int8_t q_u11[NE * 1024], q_u10[NE * 1024];
__device__ int8_t q_u21[NE * 768],  q_u20[NE * 768];

// activation row scales
__device__ float s_xe[NE], s_h[NE], s_x0[NE], s_x1[2 * NE], s_x2[2 * NE];
__device__ float s_u0[NE], s_u1[2 * NE], s_u2[2 * NE];

// ---------------- int8 weight arena + scales ----------------------------------
#define W_R1  0
#define W_R2  16384
#define W_01  409600
#define W_M11 1884160
#define W_M21 2932736
#define W_02  3522560
#define W_M12 3932160
#define W_M22 4456448
__device__ int8_t g_w1[4751360], g_w0[4751360];
// scale arena: row counts 128,3072,1152,1024,768,640,1024,768
#define S_R1  0
#define S_R2  128
#define S_01  3200
#define S_M11 4352
#define S_M21 5376
#define S_02  6144
#define S_M12 6784
#define S_M22 7808
__device__ float g_ws[8576];

// ---------------- helpers -----------------------------------------------------
__device__ __forceinline__ uint32_t smem_u32(const void* p) {
    uint32_t a;
    asm("{ .reg .u64 t; cvta.to.shared.u64 t, %1; cvt.u32.u64 %0, t; }" : "=r"(a) : "l"(p));
    return a;
}
__device__ __forceinline__ void cpa16(uint32_t dst, const void* src) {
    asm volatile("cp.async.cg.shared.global [%0], [%1], 16;" :: "r"(dst), "l"(src));
}
__device__ __forceinline__ void quant2(float v, float s, float is, int8_t* q1p, int8_t* q0p) {
    float q1f = rintf(v * is);
    float r = v - q1f * s;
    int q0 = (int)rintf(r * 254.f * is);
    q0 = max(-127, min(127, q0));
    *q1p = (int8_t)(int)q1f;
    *q0p = (int8_t)q0;
}

#define LDSM4(r, a) \
    asm volatile("ldmatrix.sync.aligned.m8n8.x4.shared.b16 {%0,%1,%2,%3}, [%4];" \
        : "=r"((r)[0]), "=r"((r)[1]), "=r"((r)[2]), "=r"((r)[3]) : "r"(a))

#define IMMA(d, a, b0_, b1_) \
    asm volatile("mma.sync.aligned.m16n8k32.row.col.s32.s8.s8.s32 " \
        "{%0,%1,%2,%3},{%4,%5,%6,%7},{%8,%9},{%0,%1,%2,%3};" \
        : "+r"((d)[0]), "+r"((d)[1]), "+r"((d)[2]), "+r"((d)[3]) \
        : "r"((a)[0]), "r"((a)[1]), "r"((a)[2]), "r"((a)[3]), "r"(b0_), "r"(b1_))

// ---------------- int8 split GEMM --------------------------------------------
// C[M,N] = s_a[m] * s_w[n] * (P11 + (P10 + P01)/254) + bias
#define RSTRIDE 80
#define TILE_SM 10240                   // 128 rows * 80 B
#define STAGE_SM (4 * TILE_SM)          // A1, A0, W1, W0
#define NST 3
#define SMEM_SZ (NST * STAGE_SM)        // 122880 B

__global__ __launch_bounds__(256, 1)
void igemm(const int8_t* __restrict__ A1, const int8_t* __restrict__ A0,
           const int8_t* __restrict__ W1, const int8_t* __restrict__ W0,
           const float* __restrict__ sA, const float* __restrict__ sW,
           const float* __restrict__ bias, float* __restrict__ C,
           int M, int N, int K)
{
    extern __shared__ char sm[];
    const uint32_t smb = smem_u32(sm);

    const int tid  = threadIdx.x;
    const int lane = tid & 31;
    const int warp = tid >> 5;
    const int wm   = warp >> 1;
    const int wn   = warp & 1;
    const int m0   = blockIdx.y * 128;
    const int n0   = blockIdx.x * 128;
    const int nch  = K >> 6;

    const int r0 = tid >> 2, c4 = tid & 3;
    const uint32_t soff0 = (uint32_t)(r0 * RSTRIDE + c4 * 16);
    int amA = m0 + r0;       if (amA >= M) amA = M - 1;
    int amB = m0 + r0 + 64;  if (amB >= M) amB = M - 1;
    const size_t offA  = (size_t)amA * K + c4 * 16;
    const size_t offA2 = (size_t)amB * K + c4 * 16;
    const size_t offW  = (size_t)(n0 + r0) * K + c4 * 16;
    const size_t offW2 = offW + (size_t)64 * K;

#define LOAD_STAGE(s, chunk) do {                                              \
    uint32_t sb_ = smb + (uint32_t)(s) * STAGE_SM;                             \
    int go_ = (chunk) * 64;                                                    \
    cpa16(sb_ + soff0,                              A1 + offA  + go_);         \
    cpa16(sb_ + 64 * RSTRIDE + soff0,               A1 + offA2 + go_);         \
    cpa16(sb_ + TILE_SM + soff0,                    A0 + offA  + go_);         \
    cpa16(sb_ + TILE_SM + 64 * RSTRIDE + soff0,     A0 + offA2 + go_);         \
    cpa16(sb_ + 2 * TILE_SM + soff0,                W1 + offW  + go_);         \
    cpa16(sb_ + 2 * TILE_SM + 64 * RSTRIDE + soff0, W1 + offW2 + go_);         \
    cpa16(sb_ + 3 * TILE_SM + soff0,                W0 + offW  + go_);         \
    cpa16(sb_ + 3 * TILE_SM + 64 * RSTRIDE + soff0, W0 + offW2 + go_);         \
    asm volatile("cp.async.commit_group;" ::: "memory");                       \
} while (0)

    LOAD_STAGE(0, 0);
    if (nch > 1) LOAD_STAGE(1, 1);
    else         asm volatile("cp.async.commit_group;" ::: "memory");

    const int aRow = wm * 32 + (lane & 15);
    const int aCol = (lane >> 4) << 4;
    const int bRow = wn * 64 + (lane & 7) + ((lane >> 4) << 3);
    const int bCol = (lane & 8) << 1;

    int hi[2][8][4], md[2][8][4];
#pragma unroll
    for (int a = 0; a < 2; a++)
#pragma unroll
        for (int b = 0; b < 8; b++)
#pragma unroll
            for (int c = 0; c < 4; c++) { hi[a][b][c] = 0; md[a][b][c] = 0; }

    for (int kc = 0; kc < nch; kc++) {
        if (kc == nch - 1) asm volatile("cp.async.wait_group 0;" ::: "memory");
        else               asm volatile("cp.async.wait_group 1;" ::: "memory");
        __syncthreads();

        const uint32_t sb = smb + (uint32_t)(kc % NST) * STAGE_SM;
#pragma unroll
        for (int ks = 0; ks < 2; ks++) {
            const int kb = ks * 32;
            uint32_t a1[2][4], a0[2][4];
#pragma unroll
            for (int mi = 0; mi < 2; mi++) {
                uint32_t ra = sb + (aRow + mi * 16) * RSTRIDE + kb + aCol;
                LDSM4(a1[mi], ra);
                LDSM4(a0[mi], ra + TILE_SM);
            }
#pragma unroll
            for (int np = 0; np < 4; np++) {
                uint32_t rb = sb + 2 * TILE_SM + (bRow + np * 16) * RSTRIDE + kb + bCol;
                uint32_t b1[4], b0[4];
                LDSM4(b1, rb);
                LDSM4(b0, rb + TILE_SM);
#pragma unroll
                for (int mi = 0; mi < 2; mi++) {
                    IMMA(hi[mi][np * 2],     a1[mi], b1[0], b1[1]);
                    IMMA(hi[mi][np * 2 + 1], a1[mi], b1[2], b1[3]);
                    IMMA(md[mi][np * 2],     a1[mi], b0[0], b0[1]);
                    IMMA(md[mi][np * 2 + 1], a1[mi], b0[2], b0[3]);
                    IMMA(md[mi][np * 2],     a0[mi], b1[0], b1[1]);
                    IMMA(md[mi][np * 2 + 1], a0[mi], b1[2], b1[3]);
                }
            }
        }
        __syncthreads();

        const int j = kc + 2;
        if (j < nch) LOAD_STAGE(j % NST, j);
    }

#pragma unroll
    for (int mi = 0; mi < 2; mi++) {
        int r = m0 + wm * 32 + mi * 16 + (lane >> 2);
        float sa0 = (r < M)     ? sA[r]     : 0.f;
        float sa8 = (r + 8 < M) ? sA[r + 8] : 0.f;
#pragma unroll
        for (int nf = 0; nf < 8; nf++) {
            int col = n0 + wn * 64 + nf * 8 + (lane & 3) * 2;
            float sw0 = sW[col], sw1 = sW[col + 1];
            float b0v = bias ? bias[col]     : 0.f;
            float b1v = bias ? bias[col + 1] : 0.f;
            const float inv = 1.f / 254.f;
            if (r < M) {
                float2 v;
                v.x = sa0 * sw0 * ((float)hi[mi][nf][0] + (float)md[mi][nf][0] * inv) + b0v;
                v.y = sa0 * sw1 * ((float)hi[mi][nf][1] + (float)md[mi][nf][1] * inv) + b1v;
                *(float2*)(C + (size_t)r * N + col) = v;
            }
            if (r + 8 < M) {
                float2 v;
                v.x = sa8 * sw0 * ((float)hi[mi][nf][2] + (float)md[mi][nf][2] * inv) + b0v;
                v.y = sa8 * sw1 * ((float)hi[mi][nf][3] + (float)md[mi][nf][3] * inv) + b1v;
                *(float2*)(C + (size_t)(r + 8) * N + col) = v;
            }
        }
    }
}

// ---------------- per-row 2-level int8 quantization (weights / x_edge) --------
__global__ __launch_bounds__(128)
void k_quant(const float* __restrict__ X, int8_t* __restrict__ Q1,
             int8_t* __restrict__ Q0, float* __restrict__ S, int K)
{
    int row = blockIdx.x, t = threadIdx.x;
    const float* xp = X + (size_t)row * K;
    float v[10];
    int n = 0;
    float mx = 0.f;
    for (int i = t; i < K; i += 128) { float a = xp[i]; v[n++] = a; mx = fmaxf(mx, fabsf(a)); }
#pragma unroll
    for (int o = 16; o > 0; o >>= 1) mx = fmaxf(mx, __shfl_xor_sync(0xffffffffu, mx, o));
    __shared__ float wmx[4];
    if ((t & 31) == 0) wmx[t >> 5] = mx;
    __syncthreads();
    mx = fmaxf(fmaxf(wmx[0], wmx[1]), fmaxf(wmx[2], wmx[3]));
    mx = fmaxf(mx, 1e-20f);
    float s  = mx * (1.f / 127.f);
    float is = 127.f / mx;
    if (t == 0) S[row] = s;
    n = 0;
    for (int i = t; i < K; i += 128)
        quant2(v[n++], s, is, &Q1[(size_t)row * K + i], &Q0[(size_t)row * K + i]);
}

// ---------------- LayerNorm + SiLU + fused quant ------------------------------
__global__ __launch_bounds__(128)
void k_ln_silu(const float* __restrict__ pre, const float* __restrict__ gam,
               const float* __restrict__ bet)
{
    int e = blockIdx.x, t = threadIdx.x;
    float v = pre[(size_t)e * 128 + t];
    __shared__ float s1[4], s2[4], sm3[4];
    float a = v, a2 = v * v;
#pragma unroll
    for (int o = 16; o > 0; o >>= 1) {
        a  += __shfl_xor_sync(0xffffffffu, a,  o);
        a2 += __shfl_xor_sync(0xffffffffu, a2, o);
    }
    int w = t >> 5;
    if ((t & 31) == 0) { s1[w] = a; s2[w] = a2; }
    __syncthreads();
    float sum = s1[0] + s1[1] + s1[2] + s1[3];
    float sq  = s2[0] + s2[1] + s2[2] + s2[3];
    float mu  = sum * (1.f / 128.f);
    float var = sq * (1.f / 128.f) - mu * mu;
    if (var < 0.f) var = 0.f;
    float h = (v - mu) * rsqrtf(var + 1e-5f) * gam[t] + bet[t];
    float o = h / (1.f + expf(-h));

    float mx = fabsf(o);
#pragma unroll
    for (int off = 16; off > 0; off >>= 1) mx = fmaxf(mx, __shfl_xor_sync(0xffffffffu, mx, off));
    if ((t & 31) == 0) sm3[w] = mx;
    __syncthreads();
    mx = fmaxf(fmaxf(sm3[0], sm3[1]), fmaxf(sm3[2], sm3[3]));
    mx = fmaxf(mx, 1e-20f);
    float s  = mx * (1.f / 127.f);
    float is = 127.f / mx;
    if (t == 0) s_h[e] = s;
    size_t idx = (size_t)e * 128 + t;
    quant2(o, s, is, &q_h1[idx], &q_h0[idx]);
}

// ---------------- rotation 1: gather + wigner + rad-scale + fused quant -------
__global__ __launch_bounds__(256)
void k_rot1(const float* __restrict__ x, const float* __restrict__ wigner,
            const int* __restrict__ edge_index)
{
    int e = blockIdx.x;
    int c = threadIdx.x;
    __shared__ float wg[19][25];
    __shared__ float wred[5][8];
    __shared__ float fscale[5];

    for (int t = c; t < 19 * 25; t += 256) {
        int k = t / 25, j = t - k * 25;
        int om = k + (k >= 9 ? 1 : 0) + (k >= 14 ? 3 : 0);
        wg[k][j] = wigner[(size_t)e * 625 + om * 25 + j];
    }

    int src = edge_index[e];
    int dst = edge_index[NE + e];
    const float* xp = x + (size_t)(c < 128 ? src : dst) * 3200 + (c & 127);
    float xr[25];
#pragma unroll
    for (int j = 0; j < 25; j++) xr[j] = xp[j * 128];
    __syncthreads();

    const float* radp = g_rad + (size_t)e * 3072;
    const int PERM_[19] = {0,2,6,11,16, 3,7,12,17, 1,5,10,15, 8,13,18, 4,9,14};

    float val[19];
    float pm[5] = {0.f, 0.f, 0.f, 0.f, 0.f};
#pragma unroll
    for (int p = 0; p < 19; p++) {
        int k = PERM_[p];
        float acc = 0.f;
#pragma unroll
        for (int j = 0; j < 25; j++) acc += wg[k][j] * xr[j];
        float rs;
        if (p < 5)       rs = radp[p * 256 + c];
        else if (p < 13) rs = radp[1280 + ((p - 5) & 3) * 256 + c];
        else             rs = radp[2304 + ((p - 13) % 3) * 256 + c];
        float v = acc * rs;
        val[p] = v;
        int row = (p < 5) ? 0 : (p < 9) ? 1 : (p < 13) ? 2 : (p < 16) ? 3 : 4;
        pm[row] = fmaxf(pm[row], fabsf(v));
    }

    int wid = c >> 5, lane = c & 31;
#pragma unroll
    for (int r = 0; r < 5; r++) {
        float m = pm[r];
#pragma unroll
        for (int o = 16; o > 0; o >>= 1) m = fmaxf(m, __shfl_xor_sync(0xffffffffu, m, o));
        if (lane == 0) wred[r][wid] = m;
    }
    __syncthreads();
    if (c < 5) {
        float m = wred[c][0];
#pragma unroll
        for (int i = 1; i < 8; i++) m = fmaxf(m, wred[c][i]);
        m = fmaxf(m, 1e-20f);
        float s = m * (1.f / 127.f);
        fscale[c] = s;
        if (c == 0) s_x0[e] = s;
        else if (c == 1) s_x1[2 * e]     = s;
        else if (c == 2) s_x1[2 * e + 1] = s;
        else if (c == 3) s_x2[2 * e]     = s;
        else             s_x2[2 * e + 1] = s;
    }
    __syncthreads();

#pragma unroll
    for (int p = 0; p < 19; p++) {
        int row = (p < 5) ? 0 : (p < 9) ? 1 : (p < 13) ? 2 : (p < 16) ? 3 : 4;
        float s  = fscale[row];
        float is = 1.f / s;
        size_t i;
        int8_t *Q1, *Q0;
        if (p < 5) {
            i = (size_t)e * 1280 + p * 256 + c;           Q1 = q_x01; Q0 = q_x00;
        } else if (p < 13) {
            int ss = (p - 5) & 3, rr = (p - 5) >> 2;
            i = ((size_t)e * 2 + rr) * 1024 + ss * 256 + c; Q1 = q_x11; Q0 = q_x10;
        } else {
            int ss = (p - 13) % 3, rr = (p - 13) / 3;
            i = ((size_t)e * 2 + rr) * 768 + ss * 256 + c;  Q1 = q_x21; Q0 = q_x20;
        }
        quant2(val[p], s, is, &Q1[i], &Q0[i]);
    }
}

// ---------------- assemble conv1 out + gating + fused quant -------------------
__global__ __launch_bounds__(128)
void k_assemble1()
{
    int e = blockIdx.x, c = threadIdx.x;
    const float* c0 = g_c0 + (size_t)e * 1152;
    __shared__ float wred[5][4];
    __shared__ float fscale[5];

    float gate[4];
#pragma unroll
    for (int l = 0; l < 4; l++) gate[l] = 1.f / (1.f + expf(-c0[l * 128 + c]));

    float v0[5], v1[8], v2[6];
    float pm[5] = {0.f, 0.f, 0.f, 0.f, 0.f};

#pragma unroll
    for (int p = 0; p < 5; p++) {
        float v = c0[512 + p * 128 + c];
        if (p == 0) v = v / (1.f + expf(-v));
        else        v *= gate[p - 1];
        v0[p] = v;
        pm[0] = fmaxf(pm[0], fabsf(v));
    }

    const float* c1a = g_c1 + (size_t)e * 2048;
    const float* c1b = c1a + 1024;
#pragma unroll
    for (int s = 0; s < 4; s++) {
        float yr0 = c1a[s * 128 + c], yi0 = c1a[512 + s * 128 + c];
        float yr1 = c1b[s * 128 + c], yi1 = c1b[512 + s * 128 + c];
        float a = (yr0 - yi1) * gate[s];
        float b = (yr1 + yi0) * gate[s];
        v1[s] = a; v1[4 + s] = b;
        pm[1] = fmaxf(pm[1], fabsf(a));
        pm[2] = fmaxf(pm[2], fabsf(b));
    }

    const float* c2a = g_c2 + (size_t)e * 1536;
    const float* c2b = c2a + 768;
#pragma unroll
    for (int s = 0; s < 3; s++) {
        float yr0 = c2a[s * 128 + c], yi0 = c2a[384 + s * 128 + c];
        float yr1 = c2b[s * 128 + c], yi1 = c2b[384 + s * 128 + c];
        float a = (yr0 - yi1) * gate[s + 1];
        float b = (yr1 + yi0) * gate[s + 1];
        v2[s] = a; v2[3 + s] = b;
        pm[3] = fmaxf(pm[3], fabsf(a));
        pm[4] = fmaxf(pm[4], fabsf(b));
    }

    int wid = c >> 5, lane = c & 31;
#pragma unroll
    for (int r = 0; r < 5; r++) {
        float m = pm[r];
#pragma unroll
        for (int o = 16; o > 0; o >>= 1) m = fmaxf(m, __shfl_xor_sync(0xffffffffu, m, o));
        if (lane == 0) wred[r][wid] = m;
    }
    __syncthreads();
    if (c < 5) {
        float m = fmaxf(fmaxf(wred[c][0], wred[c][1]), fmaxf(wred[c][2], wred[c][3]));
        m = fmaxf(m, 1e-20f);
        float s = m * (1.f / 127.f);
        fscale[c] = s;
        if (c == 0)      s_u0[e]         = s;
        else if (c == 1) s_u1[2 * e]     = s;
        else if (c == 2) s_u1[2 * e + 1] = s;
        else if (c == 3) s_u2[2 * e]     = s;
        else             s_u2[2 * e + 1] = s;
    }
    __syncthreads();

    {
        float s = fscale[0], is = 1.f / s;
#pragma unroll
        for (int p = 0; p < 5; p++) {
            size_t i = (size_t)e * 640 + p * 128 + c;
            quant2(v0[p], s, is, &q_u01[i], &q_u00[i]);
        }
    }
#pragma unroll
    for (int rr = 0; rr < 2; rr++) {
        float s = fscale[1 + rr], is = 1.f / s;
#pragma unroll
        for (int ss = 0; ss < 4; ss++) {
            size_t i = ((size_t)e * 2 + rr) * 512 + ss * 128 + c;
            quant2(v1[rr * 4 + ss], s, is, &q_u11[i], &q_u10[i]);
        }
    }
#pragma unroll
    for (int rr = 0; rr < 2; rr++) {
        float s = fscale[3 + rr], is = 1.f / s;
#pragma unroll
        for (int ss = 0; ss < 3; ss++) {
            size_t i = ((size_t)e * 2 + rr) * 384 + ss * 128 + c;
            quant2(v2[rr * 3 + ss], s, is, &q_u21[i], &q_u20[i]);
        }
    }
}

// ---------------- rotation 2 + envelope + scatter ------------------------------
__global__ __launch_bounds__(128)
void k_rot2(const float* __restrict__ wigner_inv, const float* __restrict__ edist,
            const int* __restrict__ edge_index, const int* __restrict__ node_off,
            float* __restrict__ out)
{
    int e = blockIdx.x, c = threadIdx.x;
    __shared__ float wi[625];
    __shared__ float msg[19][128];

    for (int t = c; t < 625; t += 128) wi[t] = wigner_inv[(size_t)e * 625 + t];

    float d = edist[e] * (1.f / 6.f);
    float env = 0.f;
    if (d < 1.f) {
        float d2 = d * d, d4 = d2 * d2, d5 = d4 * d;
        env = 1.f + d5 * (-21.f + d * (35.f - 15.f * d));
    }

    const float* d0  = g_d0 + (size_t)e * 640;
    const float* d1a = g_d1 + (size_t)e * 2048; const float* d1b = d1a + 1024;
    const float* d2a = g_d2 + (size_t)e * 1536; const float* d2b = d2a + 768;
    const int PERM_[19] = {0,2,6,11,16, 3,7,12,17, 1,5,10,15, 8,13,18, 4,9,14};

#pragma unroll
    for (int p = 0; p < 19; p++) {
        float v;
        if (p < 5) {
            v = d0[p * 128 + c];
        } else if (p < 13) {
            int s = (p - 5) & 3, rr = (p - 5) >> 2;
            v = (rr == 0) ? d1a[s * 128 + c] - d1b[512 + s * 128 + c]
                          : d1b[s * 128 + c] + d1a[512 + s * 128 + c];
        } else {
            int s = (p - 13) % 3, rr = (p - 13) / 3;
            v = (rr == 0) ? d2a[s * 128 + c] - d2b[384 + s * 128 + c]
                          : d2b[s * 128 + c] + d2a[384 + s * 128 + c];
        }
        msg[PERM_[p]][c] = v * env;
    }
    __syncthreads();

    int nd = edge_index[NE + e] - node_off[0];
    float* op = out + (size_t)nd * 3200 + c;
#pragma unroll
    for (int i = 0; i < 25; i++) {
        float acc = 0.f;
#pragma unroll
        for (int k = 0; k < 19; k++) {
            int om = k + (k >= 9 ? 1 : 0) + (k >= 14 ? 3 : 0);
            acc += wi[i * 25 + om] * msg[k][c];
        }
        atomicAdd(op + i * 128, acc);
    }
}

// ---------------- host launch --------------------------------------------------
extern "C" void kernel_launch(void* const* d_in, const int* in_sizes, int n_in,
                              void* d_out, int out_size)
{
    const float* x          = (const float*)d_in[0];
    const float* x_edge     = (const float*)d_in[1];
    const float* edist      = (const float*)d_in[2];
    const float* wigner     = (const float*)d_in[3];
    const float* wigner_inv = (const float*)d_in[4];
    const float* W_r1       = (const float*)d_in[5];
    const float* b_r1       = (const float*)d_in[6];
    const float* ln_g       = (const float*)d_in[7];
    const float* ln_b       = (const float*)d_in[8];
    const float* W_r2       = (const float*)d_in[9];
    const float* b_r2       = (const float*)d_in[10];
    const float* W0_1       = (const float*)d_in[11];
    const float* b0_1       = (const float*)d_in[12];
    const float* Wm1_1      = (const float*)d_in[13];
    const float* Wm2_1      = (const float*)d_in[14];
    const float* W0_2       = (const float*)d_in[15];
    const float* b0_2       = (const float*)d_in[16];
    const float* Wm1_2      = (const float*)d_in[17];
    const float* Wm2_2      = (const float*)d_in[18];
    const int*   eidx       = (const int*)d_in[19];
    const int*   noff       = (const int*)d_in[20];
    float*       out        = (float*)d_out;

    cudaFuncSetAttribute(igemm, cudaFuncAttributeMaxDynamicSharedMemorySize, SMEM_SZ);

    float *pre, *rad, *c0, *c1, *c2, *dd0, *dd1, *dd2;
    cudaGetSymbolAddress((void**)&pre, g_pre);
    cudaGetSymbolAddress((void**)&rad, g_rad);
    cudaGetSymbolAddress((void**)&c0,  g_c0);
    cudaGetSymbolAddress((void**)&c1,  g_c1);
    cudaGetSymbolAddress((void**)&c2,  g_c2);
    cudaGetSymbolAddress((void**)&dd0, g_d0);
    cudaGetSymbolAddress((void**)&dd1, g_d1);
    cudaGetSymbolAddress((void**)&dd2, g_d2);

    int8_t *w1, *w0, *xe1, *xe0, *h1, *h0, *x01, *x00, *x11, *x10, *x21, *x20;
    int8_t *u01, *u00, *u11, *u10, *u21, *u20;
    float  *ws, *sxe, *sh, *sx0, *sx1, *sx2, *su0, *su1, *su2;
    cudaGetSymbolAddress((void**)&w1,  g_w1);   cudaGetSymbolAddress((void**)&w0,  g_w0);
    cudaGetSymbolAddress((void**)&ws,  g_ws);
    cudaGetSymbolAddress((void**)&xe1, q_xe1);  cudaGetSymbolAddress((void**)&xe0, q_xe0);
    cudaGetSymbolAddress((void**)&h1,  q_h1);   cudaGetSymbolAddress((void**)&h0,  q_h0);
    cudaGetSymbolAddress((void**)&x01, q_x01);  cudaGetSymbolAddress((void**)&x00, q_x00);
    cudaGetSymbolAddress((void**)&x11, q_x11);  cudaGetSymbolAddress((void**)&x10, q_x10);
    cudaGetSymbolAddress((void**)&x21, q_x21);  cudaGetSymbolAddress((void**)&x20, q_x20);
    cudaGetSymbolAddress((void**)&u01, q_u01);  cudaGetSymbolAddress((void**)&u00, q_u00);
    cudaGetSymbolAddress((void**)&u11, q_u11);  cudaGetSymbolAddress((void**)&u10, q_u10);
    cudaGetSymbolAddress((void**)&u21, q_u21);  cudaGetSymbolAddress((void**)&u20, q_u20);
    cudaGetSymbolAddress((void**)&sxe, s_xe);   cudaGetSymbolAddress((void**)&sh,  s_h);
    cudaGetSymbolAddress((void**)&sx0, s_x0);   cudaGetSymbolAddress((void**)&sx1, s_x1);
    cudaGetSymbolAddress((void**)&sx2, s_x2);   cudaGetSymbolAddress((void**)&su0, s_u0);
    cudaGetSymbolAddress((void**)&su1, s_u1);   cudaGetSymbolAddress((void**)&su2, s_u2);

    // ---- weight + x_edge quantization (grid = ROW COUNT of each matrix) ----
    k_quant<<<128,  128>>>(W_r1,  w1 + W_R1,  w0 + W_R1,  ws + S_R1,  128);
    k_quant<<<3072, 128>>>(W_r2,  w1 + W_R2,  w0 + W_R2,  ws + S_R2,  128);
    k_quant<<<1152, 128>>>(W0_1,  w1 + W_01,  w0 + W_01,  ws + S_01,  1280);
    k_quant<<<1024, 128>>>(Wm1_1, w1 + W_M11, w0 + W_M11, ws + S_M11, 1024);
    k_quant<<<768,  128>>>(Wm2_1, w1 + W_M21, w0 + W_M21, ws + S_M21, 768);
    k_quant<<<640,  128>>>(W0_2,  w1 + W_02,  w0 + W_02,  ws + S_02,  640);
    k_quant<<<1024, 128>>>(Wm1_2, w1 + W_M12, w0 + W_M12, ws + S_M12, 512);   // 1024 rows x K=512
    k_quant<<<768,  128>>>(Wm2_2, w1 + W_M22, w0 + W_M22, ws + S_M22, 384);   // 768 rows x K=384
    k_quant<<<NE,   128>>>(x_edge, xe1, xe0, sxe, 128);

    const int gy1 = (NE + 127) / 128;        // 391
    const int gy2 = (2 * NE + 127) / 128;    // 782

    // ---- radial MLP ----
    igemm<<<dim3(1, gy1), 256, SMEM_SZ>>>(xe1, xe0, w1 + W_R1, w0 + W_R1,
                                          sxe, ws + S_R1, b_r1, pre, NE, 128, 128);
    k_ln_silu<<<NE, 128>>>(pre, ln_g, ln_b);
    igemm<<<dim3(24, gy1), 256, SMEM_SZ>>>(h1, h0, w1 + W_R2, w0 + W_R2,
                                           sh, ws + S_R2, b_r2, rad, NE, 3072, 128);

    // ---- gather + rotation + rad-scale + quant ----
    k_rot1<<<NE, 256>>>(x, wigner, eidx);

    // ---- SO2 conv 1 ----
    igemm<<<dim3(9, gy1), 256, SMEM_SZ>>>(x01, x00, w1 + W_01, w0 + W_01,
                                          sx0, ws + S_01, b0_1, c0, NE, 1152, 1280);
    igemm<<<dim3(8, gy2), 256, SMEM_SZ>>>(x11, x10, w1 + W_M11, w0 + W_M11,
                                          sx1, ws + S_M11, nullptr, c1, 2 * NE, 1024, 1024);
    igemm<<<dim3(6, gy2), 256, SMEM_SZ>>>(x21, x20, w1 + W_M21, w0 + W_M21,
                                          sx2, ws + S_M21, nullptr, c2, 2 * NE, 768, 768);

    // ---- gating / assembly + quant ----
    k_assemble1<<<NE, 128>>>();

    // ---- SO2 conv 2 ----
    igemm<<<dim3(5, gy1), 256, SMEM_SZ>>>(u01, u00, w1 + W_02, w0 + W_02,
                                          su0, ws + S_02, b0_2, dd0, NE, 640, 640);
    igemm<<<dim3(8, gy2), 256, SMEM_SZ>>>(u11, u10, w1 + W_M12, w0 + W_M12,
                                          su1, ws + S_M12, nullptr, dd1, 2 * NE, 1024, 512);
    igemm<<<dim3(6, gy2), 256, SMEM_SZ>>>(u21, u20, w1 + W_M22, w0 + W_M22,
                                          su2, ws + S_M22, nullptr, dd2, 2 * NE, 768, 384);

    // ---- inverse rotation + envelope + scatter-add ----
    cudaMemsetAsync(d_out, 0, (size_t)out_size * sizeof(float), 0);
    k_rot2<<<NE, 128>>>(wigner_inv, edist, eidx, noff, out);
}

// round 7
// speedup vs baseline: 1.8420x; 1.8420x over previous
#include <cuda_runtime.h>
#include <cuda_bf16.h>
#include <cstdint>
#include <cstddef>

#define NE 50000

typedef unsigned long long ull;
typedef __nv_bfloat16 bf16;

// ---------------- fp32 scratch (GEMM outputs / elementwise inputs) ----------
__device__ float g_pre[NE * 128];
__device__ float g_rad[NE * 3072];
__device__ float g_c0 [NE * 1152];
__device__ float g_c1 [NE * 2048];   // (2E, 1024)
__device__ float g_c2 [NE * 1536];   // (2E, 768)
__device__ float g_d0 [NE * 640];
__device__ float g_d1 [NE * 2048];   // (2E, 1024)
__device__ float g_d2 [NE * 1536];   // (2E, 768)

// ---------------- bf16 split activations (GEMM A operands) ------------------
__device__ bf16 g_xe_h[NE * 128],  g_xe_l[NE * 128];
__device__ bf16 g_h_h [NE * 128],  g_h_l [NE * 128];
__device__ bf16 g_x0_h[NE * 1280], g_x0_l[NE * 1280];
__device__ bf16 g_x1_h[NE * 2048], g_x1_l[NE * 2048];
__device__ bf16 g_x2_h[NE * 1536], g_x2_l[NE * 1536];
__device__ bf16 g_u0_h[NE * 640],  g_u0_l[NE * 640];
__device__ bf16 g_u1_h[NE * 1024], g_u1_l[NE * 1024];
__device__ bf16 g_u2_h[NE * 768],  g_u2_l[NE * 768];

// ---------------- bf16 split weight arena ------------------------------------
#define W_R1  0
#define W_R2  16384
#define W_01  409600
#define W_M11 1884160
#define W_M21 2932736
#define W_02  3522560
#define W_M12 3932160
#define W_M22 4456448
__device__ bf16 g_w_h[4751360], g_w_l[4751360];

// ---------------- helpers -----------------------------------------------------
__device__ __forceinline__ uint32_t smem_u32(const void* p) {
    uint32_t a;
    asm("{ .reg .u64 t; cvta.to.shared.u64 t, %1; cvt.u32.u64 %0, t; }" : "=r"(a) : "l"(p));
    return a;
}
__device__ __forceinline__ void bsplit(float v, bf16* ph, bf16* pl) {
    bf16 h = __float2bfloat16(v);
    *ph = h;
    *pl = __float2bfloat16(v - __bfloat162float(h));
}
__device__ __forceinline__ void cpa16(uint32_t dst, const void* src) {
    asm volatile("cp.async.cg.shared.global [%0], [%1], 16;" :: "r"(dst), "l"(src));
}

#define LDSM4(r, a) \
    asm volatile("ldmatrix.sync.aligned.m8n8.x4.shared.b16 {%0,%1,%2,%3}, [%4];" \
        : "=r"((r)[0]), "=r"((r)[1]), "=r"((r)[2]), "=r"((r)[3]) : "r"(a))

#define MMA(d, a, b0, b1) \
    asm volatile("mma.sync.aligned.m16n8k16.row.col.f32.bf16.bf16.f32 " \
        "{%0,%1,%2,%3},{%4,%5,%6,%7},{%8,%9},{%0,%1,%2,%3};" \
        : "+f"((d)[0]), "+f"((d)[1]), "+f"((d)[2]), "+f"((d)[3]) \
        : "r"((a)[0]), "r"((a)[1]), "r"((a)[2]), "r"((a)[3]), "r"(b0), "r"(b1))

// ---------------- mma.sync split-bf16 GEMM ------------------------------------
// C[M,N] = (Ah+Al)[M,K] @ (Wh+Wl)[N,K]^T + bias   (lo*lo dropped)
// CTA tile 256x128, K-chunk 32 bf16, 8 warps (4m x 2n), warp tile 64x64.
#define RSTRIDE 80                        // bytes per smem row (32 bf16 + pad)
#define AH_OFF 0
#define AL_OFF 20480                      // 256 rows * 80
#define WH_OFF 40960
#define WL_OFF 51200                      // WH + 128*80
#define STAGE_SM 61440                    // 768 rows * 80
#define NST 3
#define SMEM_SZ (NST * STAGE_SM)          // 184320 B

__global__ __launch_bounds__(256, 1)
void tcgemm(const bf16* __restrict__ Ah, const bf16* __restrict__ Al,
            const bf16* __restrict__ Wh, const bf16* __restrict__ Wl,
            const float* __restrict__ bias, float* __restrict__ C,
            int M, int N, int K)
{
    extern __shared__ char sm[];
    const uint32_t smb = smem_u32(sm);

    const int tid  = threadIdx.x;
    const int lane = tid & 31;
    const int warp = tid >> 5;
    const int wm   = warp >> 1;           // 0..3 (m block of 64)
    const int wn   = warp & 1;            // 0..1 (n block of 64)
    const int m0   = blockIdx.y * 256;
    const int n0   = blockIdx.x * 128;
    const int nch  = K >> 5;              // chunks of 32 bf16

    // ---- load descriptors: thread t owns A rows {t} (4x16B each for hi,lo)
    //      and W row t>>1 (2x16B each for hi,lo)
    int am = m0 + tid; if (am >= M) am = M - 1;
    const char* pAh = (const char*)(Ah + (size_t)am * K);
    const char* pAl = (const char*)(Al + (size_t)am * K);
    const int wr = n0 + (tid >> 1);
    const char* pWh = (const char*)(Wh + (size_t)wr * K);
    const char* pWl = (const char*)(Wl + (size_t)wr * K);
    const int wco = (tid & 1) * 32;       // byte offset within 64B chunk
    const uint32_t sAh = smb + AH_OFF + tid * RSTRIDE;
    const uint32_t sAl = smb + AL_OFF + tid * RSTRIDE;
    const uint32_t sWh = smb + WH_OFF + (tid >> 1) * RSTRIDE + wco;
    const uint32_t sWl = smb + WL_OFF + (tid >> 1) * RSTRIDE + wco;

#define LOAD_STAGE(s, chunk) do {                                         \
    uint32_t sb_ = (uint32_t)(s) * STAGE_SM;                              \
    int go_ = (chunk) * 64;                                               \
    cpa16(sAh + sb_,      pAh + go_);                                     \
    cpa16(sAh + sb_ + 16, pAh + go_ + 16);                                \
    cpa16(sAh + sb_ + 32, pAh + go_ + 32);                                \
    cpa16(sAh + sb_ + 48, pAh + go_ + 48);                                \
    cpa16(sAl + sb_,      pAl + go_);                                     \
    cpa16(sAl + sb_ + 16, pAl + go_ + 16);                                \
    cpa16(sAl + sb_ + 32, pAl + go_ + 32);                                \
    cpa16(sAl + sb_ + 48, pAl + go_ + 48);                                \
    cpa16(sWh + sb_,      pWh + go_ + wco);                               \
    cpa16(sWh + sb_ + 16, pWh + go_ + wco + 16);                          \
    cpa16(sWl + sb_,      pWl + go_ + wco);                               \
    cpa16(sWl + sb_ + 16, pWl + go_ + wco + 16);                          \
    asm volatile("cp.async.commit_group;" ::: "memory");                  \
} while (0)

    LOAD_STAGE(0, 0);
    LOAD_STAGE(1, 1);

    // ldmatrix lane addressing
    const int aRow = wm * 64 + (lane & 15);
    const int aCol = (lane >> 4) << 4;
    const int bRow = wn * 64 + (lane & 7) + ((lane >> 4) << 3);
    const int bCol = (lane & 8) << 1;

    float acc[4][8][4];
#pragma unroll
    for (int a = 0; a < 4; a++)
#pragma unroll
        for (int b = 0; b < 8; b++)
#pragma unroll
            for (int c = 0; c < 4; c++) acc[a][b][c] = 0.f;

    for (int kc = 0; kc < nch; kc++) {
        if (kc == nch - 1) asm volatile("cp.async.wait_group 0;" ::: "memory");
        else               asm volatile("cp.async.wait_group 1;" ::: "memory");
        __syncthreads();

        const uint32_t sb = smb + (uint32_t)(kc % NST) * STAGE_SM;
#pragma unroll
        for (int ks = 0; ks < 2; ks++) {
            const int kb = ks * 32;
            uint32_t a1[4][4], a0[4][4];
#pragma unroll
            for (int mi = 0; mi < 4; mi++) {
                uint32_t ra = sb + AH_OFF + (aRow + mi * 16) * RSTRIDE + kb + aCol;
                LDSM4(a1[mi], ra);
                LDSM4(a0[mi], ra + (AL_OFF - AH_OFF));
            }
#pragma unroll
            for (int np = 0; np < 4; np++) {
                uint32_t rb = sb + WH_OFF + (bRow + np * 16) * RSTRIDE + kb + bCol;
                uint32_t bh[4], bl[4];
                LDSM4(bh, rb);
                LDSM4(bl, rb + (WL_OFF - WH_OFF));
#pragma unroll
                for (int mi = 0; mi < 4; mi++) {
                    float* d0 = acc[mi][np * 2];
                    float* d1 = acc[mi][np * 2 + 1];
                    MMA(d0, a1[mi], bh[0], bh[1]);
                    MMA(d1, a1[mi], bh[2], bh[3]);
                    MMA(d0, a1[mi], bl[0], bl[1]);
                    MMA(d1, a1[mi], bl[2], bl[3]);
                    MMA(d0, a0[mi], bh[0], bh[1]);
                    MMA(d1, a0[mi], bh[2], bh[3]);
                }
            }
        }
        __syncthreads();

        const int j = kc + 2;
        if (j < nch) LOAD_STAGE(j % NST, j);
    }

    // ---- epilogue ----
#pragma unroll
    for (int mi = 0; mi < 4; mi++) {
        int r0 = m0 + wm * 64 + mi * 16 + (lane >> 2);
#pragma unroll
        for (int nf = 0; nf < 8; nf++) {
            int col = n0 + wn * 64 + nf * 8 + (lane & 3) * 2;
            float b0 = bias ? bias[col]     : 0.f;
            float b1 = bias ? bias[col + 1] : 0.f;
            if (r0 < M) {
                float2 v = make_float2(acc[mi][nf][0] + b0, acc[mi][nf][1] + b1);
                *(float2*)(C + (size_t)r0 * N + col) = v;
            }
            if (r0 + 8 < M) {
                float2 v = make_float2(acc[mi][nf][2] + b0, acc[mi][nf][3] + b1);
                *(float2*)(C + (size_t)(r0 + 8) * N + col) = v;
            }
        }
    }
}

// ---------------- elementwise split ------------------------------------------
__global__ __launch_bounds__(256)
void k_split(const float* __restrict__ s, bf16* __restrict__ h, bf16* __restrict__ l, int n)
{
    int i = blockIdx.x * 256 + threadIdx.x;
    int stride = gridDim.x * 256;
    for (; i < n; i += stride) bsplit(s[i], &h[i], &l[i]);
}

// ---------------- LayerNorm + SiLU -> bf16 split -----------------------------
__global__ __launch_bounds__(128)
void k_ln_silu(const float* __restrict__ pre, const float* __restrict__ gam,
               const float* __restrict__ bet)
{
    int e = blockIdx.x, t = threadIdx.x;
    float v = pre[(size_t)e * 128 + t];
    __shared__ float s1[4], s2[4];
    float a = v, a2 = v * v;
#pragma unroll
    for (int o = 16; o > 0; o >>= 1) {
        a  += __shfl_xor_sync(0xffffffffu, a,  o);
        a2 += __shfl_xor_sync(0xffffffffu, a2, o);
    }
    int w = t >> 5;
    if ((t & 31) == 0) { s1[w] = a; s2[w] = a2; }
    __syncthreads();
    float sum = s1[0] + s1[1] + s1[2] + s1[3];
    float sq  = s2[0] + s2[1] + s2[2] + s2[3];
    float mu  = sum * (1.f / 128.f);
    float var = sq * (1.f / 128.f) - mu * mu;
    if (var < 0.f) var = 0.f;
    float h = (v - mu) * rsqrtf(var + 1e-5f) * gam[t] + bet[t];
    float o = h / (1.f + expf(-h));
    size_t idx = (size_t)e * 128 + t;
    bsplit(o, &g_h_h[idx], &g_h_l[idx]);
}

// ---------------- rotation 1: gather + wigner + perm + rad-scale -> splits ---
__global__ __launch_bounds__(256)
void k_rot1(const float* __restrict__ x, const float* __restrict__ wigner,
            const int* __restrict__ edge_index)
{
    int e = blockIdx.x;
    int c = threadIdx.x;
    __shared__ float wg[19][25];

    for (int t = c; t < 19 * 25; t += 256) {
        int k = t / 25, j = t - k * 25;
        int om = k + (k >= 9 ? 1 : 0) + (k >= 14 ? 3 : 0);
        wg[k][j] = wigner[(size_t)e * 625 + om * 25 + j];
    }

    int src = edge_index[e];
    int dst = edge_index[NE + e];
    const float* xp = x + (size_t)(c < 128 ? src : dst) * 3200 + (c & 127);
    float xr[25];
#pragma unroll
    for (int j = 0; j < 25; j++) xr[j] = xp[j * 128];
    __syncthreads();

    const float* radp = g_rad + (size_t)e * 3072;
    const int PERM_[19] = {0,2,6,11,16, 3,7,12,17, 1,5,10,15, 8,13,18, 4,9,14};

#pragma unroll
    for (int p = 0; p < 19; p++) {
        int k = PERM_[p];
        float acc = 0.f;
#pragma unroll
        for (int j = 0; j < 25; j++) acc += wg[k][j] * xr[j];

        if (p < 5) {
            float v = acc * radp[p * 256 + c];
            size_t i = (size_t)e * 1280 + p * 256 + c;
            bsplit(v, &g_x0_h[i], &g_x0_l[i]);
        } else if (p < 13) {
            int s = (p - 5) & 3, rr = (p - 5) >> 2;
            float v = acc * radp[1280 + s * 256 + c];
            size_t i = ((size_t)e * 2 + rr) * 1024 + s * 256 + c;
            bsplit(v, &g_x1_h[i], &g_x1_l[i]);
        } else {
            int s = (p - 13) % 3, rr = (p - 13) / 3;
            float v = acc * radp[2304 + s * 256 + c];
            size_t i = ((size_t)e * 2 + rr) * 768 + s * 256 + c;
            bsplit(v, &g_x2_h[i], &g_x2_l[i]);
        }
    }
}

// ---------------- assemble conv1 out + gating -> conv2 inputs (splits) -------
__global__ __launch_bounds__(128)
void k_assemble1()
{
    int e = blockIdx.x, c = threadIdx.x;
    const float* c0 = g_c0 + (size_t)e * 1152;

    float gate[4];
#pragma unroll
    for (int l = 0; l < 4; l++) gate[l] = 1.f / (1.f + expf(-c0[l * 128 + c]));

#pragma unroll
    for (int p = 0; p < 5; p++) {
        float v = c0[512 + p * 128 + c];
        if (p == 0) v = v / (1.f + expf(-v));
        else        v *= gate[p - 1];
        size_t i = (size_t)e * 640 + p * 128 + c;
        bsplit(v, &g_u0_h[i], &g_u0_l[i]);
    }

    const float* c1a = g_c1 + (size_t)e * 2048;
    const float* c1b = c1a + 1024;
#pragma unroll
    for (int s = 0; s < 4; s++) {
        float yr0 = c1a[s * 128 + c], yi0 = c1a[512 + s * 128 + c];
        float yr1 = c1b[s * 128 + c], yi1 = c1b[512 + s * 128 + c];
        size_t i0 = ((size_t)e * 2 + 0) * 512 + s * 128 + c;
        size_t i1 = ((size_t)e * 2 + 1) * 512 + s * 128 + c;
        bsplit((yr0 - yi1) * gate[s], &g_u1_h[i0], &g_u1_l[i0]);
        bsplit((yr1 + yi0) * gate[s], &g_u1_h[i1], &g_u1_l[i1]);
    }

    const float* c2a = g_c2 + (size_t)e * 1536;
    const float* c2b = c2a + 768;
#pragma unroll
    for (int s = 0; s < 3; s++) {
        float yr0 = c2a[s * 128 + c], yi0 = c2a[384 + s * 128 + c];
        float yr1 = c2b[s * 128 + c], yi1 = c2b[384 + s * 128 + c];
        size_t i0 = ((size_t)e * 2 + 0) * 384 + s * 128 + c;
        size_t i1 = ((size_t)e * 2 + 1) * 384 + s * 128 + c;
        bsplit((yr0 - yi1) * gate[s + 1], &g_u2_h[i0], &g_u2_l[i0]);
        bsplit((yr1 + yi0) * gate[s + 1], &g_u2_h[i1], &g_u2_l[i1]);
    }
}

// ---------------- rotation 2: combine + envelope + wigner_inv + scatter ------
__global__ __launch_bounds__(128)
void k_rot2(const float* __restrict__ wigner_inv, const float* __restrict__ edist,
            const int* __restrict__ edge_index, const int* __restrict__ node_off,
            float* __restrict__ out)
{
    int e = blockIdx.x, c = threadIdx.x;
    __shared__ float wi[625];
    __shared__ float msg[19][128];

    for (int t = c; t < 625; t += 128) wi[t] = wigner_inv[(size_t)e * 625 + t];

    float d = edist[e] * (1.f / 6.f);
    float env = 0.f;
    if (d < 1.f) {
        float d2 = d * d, d4 = d2 * d2, d5 = d4 * d;
        env = 1.f + d5 * (-21.f + d * (35.f - 15.f * d));
    }

    const float* d0  = g_d0 + (size_t)e * 640;
    const float* d1a = g_d1 + (size_t)e * 2048; const float* d1b = d1a + 1024;
    const float* d2a = g_d2 + (size_t)e * 1536; const float* d2b = d2a + 768;
    const int PERM_[19] = {0,2,6,11,16, 3,7,12,17, 1,5,10,15, 8,13,18, 4,9,14};

#pragma unroll
    for (int p = 0; p < 19; p++) {
        float v;
        if (p < 5) {
            v = d0[p * 128 + c];
        } else if (p < 13) {
            int s = (p - 5) & 3, rr = (p - 5) >> 2;
            v = (rr == 0) ? d1a[s * 128 + c] - d1b[512 + s * 128 + c]
                          : d1b[s * 128 + c] + d1a[512 + s * 128 + c];
        } else {
            int s = (p - 13) % 3, rr = (p - 13) / 3;
            v = (rr == 0) ? d2a[s * 128 + c] - d2b[384 + s * 128 + c]
                          : d2b[s * 128 + c] + d2a[384 + s * 128 + c];
        }
        msg[PERM_[p]][c] = v * env;
    }
    __syncthreads();

    int nd = edge_index[NE + e] - node_off[0];
    float* op = out + (size_t)nd * 3200 + c;
#pragma unroll
    for (int i = 0; i < 25; i++) {
        float acc = 0.f;
#pragma unroll
        for (int k = 0; k < 19; k++) {
            int om = k + (k >= 9 ? 1 : 0) + (k >= 14 ? 3 : 0);
            acc += wi[i * 25 + om] * msg[k][c];
        }
        atomicAdd(op + i * 128, acc);
    }
}

// ---------------- host launch -------------------------------------------------
extern "C" void kernel_launch(void* const* d_in, const int* in_sizes, int n_in,
                              void* d_out, int out_size)
{
    const float* x          = (const float*)d_in[0];
    const float* x_edge     = (const float*)d_in[1];
    const float* edist      = (const float*)d_in[2];
    const float* wigner     = (const float*)d_in[3];
    const float* wigner_inv = (const float*)d_in[4];
    const float* W_r1       = (const float*)d_in[5];
    const float* b_r1       = (const float*)d_in[6];
    const float* ln_g       = (const float*)d_in[7];
    const float* ln_b       = (const float*)d_in[8];
    const float* W_r2       = (const float*)d_in[9];
    const float* b_r2       = (const float*)d_in[10];
    const float* W0_1       = (const float*)d_in[11];
    const float* b0_1       = (const float*)d_in[12];
    const float* Wm1_1      = (const float*)d_in[13];
    const float* Wm2_1      = (const float*)d_in[14];
    const float* W0_2       = (const float*)d_in[15];
    const float* b0_2       = (const float*)d_in[16];
    const float* Wm1_2      = (const float*)d_in[17];
    const float* Wm2_2      = (const float*)d_in[18];
    const int*   eidx       = (const int*)d_in[19];
    const int*   noff       = (const int*)d_in[20];
    float*       out        = (float*)d_out;

    cudaFuncSetAttribute(tcgemm, cudaFuncAttributeMaxDynamicSharedMemorySize, SMEM_SZ);

    float *pre, *rad, *c0, *c1, *c2, *dd0, *dd1, *dd2;
    bf16 *xeh, *xel, *hh, *hl, *x0h, *x0l, *x1h, *x1l, *x2h, *x2l;
    bf16 *u0h, *u0l, *u1h, *u1l, *u2h, *u2l, *wh, *wl;
    cudaGetSymbolAddress((void**)&pre, g_pre);
    cudaGetSymbolAddress((void**)&rad, g_rad);
    cudaGetSymbolAddress((void**)&c0,  g_c0);
    cudaGetSymbolAddress((void**)&c1,  g_c1);
    cudaGetSymbolAddress((void**)&c2,  g_c2);
    cudaGetSymbolAddress((void**)&dd0, g_d0);
    cudaGetSymbolAddress((void**)&dd1, g_d1);
    cudaGetSymbolAddress((void**)&dd2, g_d2);
    cudaGetSymbolAddress((void**)&xeh, g_xe_h); cudaGetSymbolAddress((void**)&xel, g_xe_l);
    cudaGetSymbolAddress((void**)&hh,  g_h_h);  cudaGetSymbolAddress((void**)&hl,  g_h_l);
    cudaGetSymbolAddress((void**)&x0h, g_x0_h); cudaGetSymbolAddress((void**)&x0l, g_x0_l);
    cudaGetSymbolAddress((void**)&x1h, g_x1_h); cudaGetSymbolAddress((void**)&x1l, g_x1_l);
    cudaGetSymbolAddress((void**)&x2h, g_x2_h); cudaGetSymbolAddress((void**)&x2l, g_x2_l);
    cudaGetSymbolAddress((void**)&u0h, g_u0_h); cudaGetSymbolAddress((void**)&u0l, g_u0_l);
    cudaGetSymbolAddress((void**)&u1h, g_u1_h); cudaGetSymbolAddress((void**)&u1l, g_u1_l);
    cudaGetSymbolAddress((void**)&u2h, g_u2_h); cudaGetSymbolAddress((void**)&u2l, g_u2_l);
    cudaGetSymbolAddress((void**)&wh,  g_w_h);  cudaGetSymbolAddress((void**)&wl,  g_w_l);

    // weight + input splits
    k_split<<<64,  256>>>(W_r1,  wh + W_R1,  wl + W_R1,  16384);
    k_split<<<128, 256>>>(W_r2,  wh + W_R2,  wl + W_R2,  393216);
    k_split<<<256, 256>>>(W0_1,  wh + W_01,  wl + W_01,  1474560);
    k_split<<<256, 256>>>(Wm1_1, wh + W_M11, wl + W_M11, 1048576);
    k_split<<<256, 256>>>(Wm2_1, wh + W_M21, wl + W_M21, 589824);
    k_split<<<256, 256>>>(W0_2,  wh + W_02,  wl + W_02,  409600);
    k_split<<<256, 256>>>(Wm1_2, wh + W_M12, wl + W_M12, 524288);
    k_split<<<256, 256>>>(Wm2_2, wh + W_M22, wl + W_M22, 294912);
    k_split<<<512, 256>>>(x_edge, xeh, xel, NE * 128);

    const int gy1 = (NE + 255) / 256;            // 196
    const int gy2 = (2 * NE + 255) / 256;        // 391

    // radial MLP
    tcgemm<<<dim3(1, gy1), 256, SMEM_SZ>>>(xeh, xel, wh + W_R1, wl + W_R1, b_r1, pre, NE, 128, 128);
    k_ln_silu<<<NE, 128>>>(pre, ln_g, ln_b);
    tcgemm<<<dim3(24, gy1), 256, SMEM_SZ>>>(hh, hl, wh + W_R2, wl + W_R2, b_r2, rad, NE, 3072, 128);

    // gather + wigner rotation + rad scaling (writes bf16 splits)
    k_rot1<<<NE, 256>>>(x, wigner, eidx);

    // SO2 conv 1
    tcgemm<<<dim3(9, gy1), 256, SMEM_SZ>>>(x0h, x0l, wh + W_01,  wl + W_01,  b0_1,    c0, NE,     1152, 1280);
    tcgemm<<<dim3(8, gy2), 256, SMEM_SZ>>>(x1h, x1l, wh + W_M11, wl + W_M11, nullptr, c1, 2 * NE, 1024, 1024);
    tcgemm<<<dim3(6, gy2), 256, SMEM_SZ>>>(x2h, x2l, wh + W_M21, wl + W_M21, nullptr, c2, 2 * NE, 768,  768);

    // gating / assembly (writes bf16 splits)
    k_assemble1<<<NE, 128>>>();

    // SO2 conv 2
    tcgemm<<<dim3(5, gy1), 256, SMEM_SZ>>>(u0h, u0l, wh + W_02,  wl + W_02,  b0_2,    dd0, NE,     640,  640);
    tcgemm<<<dim3(8, gy2), 256, SMEM_SZ>>>(u1h, u1l, wh + W_M12, wl + W_M12, nullptr, dd1, 2 * NE, 1024, 512);
    tcgemm<<<dim3(6, gy2), 256, SMEM_SZ>>>(u2h, u2l, wh + W_M22, wl + W_M22, nullptr, dd2, 2 * NE, 768,  384);

    // inverse rotation + envelope + scatter-add
    cudaMemsetAsync(d_out, 0, (size_t)out_size * sizeof(float), 0);
    k_rot2<<<NE, 128>>>(wigner_inv, edist, eidx, noff, out);
}

// round 8
// speedup vs baseline: 2.5260x; 1.3714x over previous
#include <cuda_runtime.h>
#include <cuda_bf16.h>
#include <cstdint>
#include <cstddef>

#define NE 50000

typedef unsigned long long ull;
typedef __nv_bfloat16 bf16;

// ---------------- fp32 scratch (GEMM outputs / elementwise inputs) ----------
__device__ float g_pre[NE * 128];
__device__ float g_rad[NE * 3072];
__device__ float g_c0 [NE * 1152];
__device__ float g_c1 [NE * 2048];   // (2E, 1024)
__device__ float g_c2 [NE * 1536];   // (2E, 768)
__device__ float g_d0 [NE * 640];
__device__ float g_d1 [NE * 2048];   // (2E, 1024)
__device__ float g_d2 [NE * 1536];   // (2E, 768)

// ---------------- bf16 split activations (GEMM A operands) ------------------
__device__ bf16 g_xe_h[NE * 128],  g_xe_l[NE * 128];
__device__ bf16 g_h_h [NE * 128],  g_h_l [NE * 128];
__device__ bf16 g_x0_h[NE * 1280], g_x0_l[NE * 1280];
__device__ bf16 g_x1_h[NE * 2048], g_x1_l[NE * 2048];
__device__ bf16 g_x2_h[NE * 1536], g_x2_l[NE * 1536];
__device__ bf16 g_u0_h[NE * 640],  g_u0_l[NE * 640];
__device__ bf16 g_u1_h[NE * 1024], g_u1_l[NE * 1024];
__device__ bf16 g_u2_h[NE * 768],  g_u2_l[NE * 768];

// ---------------- bf16 split weight arena ------------------------------------
#define W_R1  0
#define W_R2  16384
#define W_01  409600
#define W_M11 1884160
#define W_M21 2932736
#define W_02  3522560
#define W_M12 3932160
#define W_M22 4456448
__device__ bf16 g_w_h[4751360], g_w_l[4751360];

// ---------------- helpers -----------------------------------------------------
__device__ __forceinline__ uint32_t smem_u32(const void* p) {
    uint32_t a;
    asm("{ .reg .u64 t; cvta.to.shared.u64 t, %1; cvt.u32.u64 %0, t; }" : "=r"(a) : "l"(p));
    return a;
}
__device__ __forceinline__ void bsplit(float v, bf16* ph, bf16* pl) {
    bf16 h = __float2bfloat16(v);
    *ph = h;
    *pl = __float2bfloat16(v - __bfloat162float(h));
}
__device__ __forceinline__ void cpa16(uint32_t dst, const void* src) {
    asm volatile("cp.async.cg.shared.global [%0], [%1], 16;" :: "r"(dst), "l"(src));
}

#define LDSM4(r, a) \
    asm volatile("ldmatrix.sync.aligned.m8n8.x4.shared.b16 {%0,%1,%2,%3}, [%4];" \
        : "=r"((r)[0]), "=r"((r)[1]), "=r"((r)[2]), "=r"((r)[3]) : "r"(a))

#define MMA(d, a, b0, b1) \
    asm volatile("mma.sync.aligned.m16n8k16.row.col.f32.bf16.bf16.f32 " \
        "{%0,%1,%2,%3},{%4,%5,%6,%7},{%8,%9},{%0,%1,%2,%3};" \
        : "+f"((d)[0]), "+f"((d)[1]), "+f"((d)[2]), "+f"((d)[3]) \
        : "r"((a)[0]), "r"((a)[1]), "r"((a)[2]), "r"((a)[3]), "r"(b0), "r"(b1))

// ---------------- mma.sync split-bf16 GEMM ------------------------------------
// C[M,N] = (Ah+Al)[M,K] @ (Wh+Wl)[N,K]^T + bias   (lo*lo dropped)
// CTA tile 128x128, K-chunk 32, 8 warps (4m x 2n), warp tile 32x64.
// Swizzled 64B smem rows (c16 ^= (row>>1)&3) -> conflict-free ldmatrix,
// 3-stage cp.async pipeline, single __syncthreads per chunk, 2 CTAs/SM.
#define TILE_SM 8192                    // 128 rows * 64 B
#define STAGE_SM (4 * TILE_SM)          // Ah, Al, Wh, Wl = 32768 B
#define NST 3
#define SMEM_SZ (NST * STAGE_SM)        // 98304 B

__device__ __forceinline__ uint32_t swz(uint32_t row, uint32_t cbyte) {
    return row * 64 + (cbyte ^ (((row >> 1) & 3) << 4));
}

__global__ __launch_bounds__(256, 2)
void tcgemm(const bf16* __restrict__ Ah, const bf16* __restrict__ Al,
            const bf16* __restrict__ Wh, const bf16* __restrict__ Wl,
            const float* __restrict__ bias, float* __restrict__ C,
            int M, int N, int K)
{
    extern __shared__ char sm[];
    const uint32_t smb = smem_u32(sm);

    const int tid  = threadIdx.x;
    const int lane = tid & 31;
    const int warp = tid >> 5;
    const int wm   = warp >> 1;          // 0..3  (m block of 32)
    const int wn   = warp & 1;           // 0..1  (n block of 64)
    const int m0   = blockIdx.y * 128;
    const int n0   = blockIdx.x * 128;
    const int nch  = K >> 5;             // K chunks of 32 bf16 (64 B rows)

    // ---- per-thread load descriptors: 8 chunks of 16B per stage ----
    const char* gbase[8];
    uint32_t    soff[8];
#pragma unroll
    for (int i = 0; i < 8; i++) {
        int idx  = tid + i * 256;        // 0..2047
        int tile = idx >> 9;             // 0:Ah 1:Al 2:Wh 3:Wl
        int rem  = idx & 511;
        int row  = rem >> 2;
        int c4   = rem & 3;
        soff[i]  = (uint32_t)(tile * TILE_SM) + swz((uint32_t)row, (uint32_t)(c4 * 16));
        const bf16* src;
        int gr;
        if (tile < 2) {
            gr = m0 + row; if (gr >= M) gr = M - 1;
            src = (tile == 0) ? Ah : Al;
        } else {
            gr = n0 + row;
            src = (tile == 2) ? Wh : Wl;
        }
        gbase[i] = (const char*)(src + (size_t)gr * K) + c4 * 16;
    }

#define LOAD_STAGE(s, chunk) do {                                          \
    uint32_t sb_ = smb + (uint32_t)(s) * STAGE_SM;                         \
    int go_ = (chunk) * 64;                                                \
    cpa16(sb_ + soff[0], gbase[0] + go_);                                  \
    cpa16(sb_ + soff[1], gbase[1] + go_);                                  \
    cpa16(sb_ + soff[2], gbase[2] + go_);                                  \
    cpa16(sb_ + soff[3], gbase[3] + go_);                                  \
    cpa16(sb_ + soff[4], gbase[4] + go_);                                  \
    cpa16(sb_ + soff[5], gbase[5] + go_);                                  \
    cpa16(sb_ + soff[6], gbase[6] + go_);                                  \
    cpa16(sb_ + soff[7], gbase[7] + go_);                                  \
    asm volatile("cp.async.commit_group;" ::: "memory");                   \
} while (0)

    // prologue: stages 0 and 1
    LOAD_STAGE(0, 0);
    LOAD_STAGE(1, 1);

    // ---- ldmatrix lane addressing (row + in-row byte col, pre-swizzle) ----
    const int aRow = wm * 32 + (lane & 15);          // + mi*16
    const int aCol = (lane >> 4) << 4;               // 0 or 16 B
    const int bRow = wn * 64 + (lane & 7) + ((lane >> 4) << 3);   // + np*16
    const int bCol = (lane & 8) << 1;                // 0 or 16 B

    float acc[2][8][4];
#pragma unroll
    for (int a = 0; a < 2; a++)
#pragma unroll
        for (int b = 0; b < 8; b++)
#pragma unroll
            for (int c = 0; c < 4; c++) acc[a][b][c] = 0.f;

    for (int kc = 0; kc < nch; kc++) {
        if (kc == nch - 1) asm volatile("cp.async.wait_group 0;" ::: "memory");
        else               asm volatile("cp.async.wait_group 1;" ::: "memory");
        __syncthreads();

        // issue next load immediately (targets stage consumed at kc-1; safe past sync)
        const int j = kc + 2;
        if (j < nch) LOAD_STAGE(j % NST, j);

        const uint32_t sb = smb + (uint32_t)(kc % NST) * STAGE_SM;
#pragma unroll
        for (int ks = 0; ks < 2; ks++) {
            const int kb = ks * 32;      // byte offset within row
            uint32_t a1[2][4], a0[2][4];
#pragma unroll
            for (int mi = 0; mi < 2; mi++) {
                uint32_t row = (uint32_t)(aRow + mi * 16);
                uint32_t ra = sb + swz(row, (uint32_t)(kb + aCol));
                LDSM4(a1[mi], ra);
                LDSM4(a0[mi], ra + TILE_SM);
            }
#pragma unroll
            for (int np = 0; np < 4; np++) {
                uint32_t row = (uint32_t)(bRow + np * 16);
                uint32_t rb = sb + 2 * TILE_SM + swz(row, (uint32_t)(kb + bCol));
                uint32_t bh[4], bl[4];
                LDSM4(bh, rb);
                LDSM4(bl, rb + TILE_SM);
#pragma unroll
                for (int mi = 0; mi < 2; mi++) {
                    float* d0 = acc[mi][np * 2];
                    float* d1 = acc[mi][np * 2 + 1];
                    MMA(d0, a1[mi], bh[0], bh[1]);
                    MMA(d1, a1[mi], bh[2], bh[3]);
                    MMA(d0, a1[mi], bl[0], bl[1]);
                    MMA(d1, a1[mi], bl[2], bl[3]);
                    MMA(d0, a0[mi], bh[0], bh[1]);
                    MMA(d1, a0[mi], bh[2], bh[3]);
                }
            }
        }
    }

    // ---- epilogue ----
#pragma unroll
    for (int mi = 0; mi < 2; mi++) {
        int r0 = m0 + wm * 32 + mi * 16 + (lane >> 2);
#pragma unroll
        for (int nf = 0; nf < 8; nf++) {
            int col = n0 + wn * 64 + nf * 8 + (lane & 3) * 2;
            float b0 = bias ? bias[col]     : 0.f;
            float b1 = bias ? bias[col + 1] : 0.f;
            if (r0 < M) {
                float2 v = make_float2(acc[mi][nf][0] + b0, acc[mi][nf][1] + b1);
                *(float2*)(C + (size_t)r0 * N + col) = v;
            }
            if (r0 + 8 < M) {
                float2 v = make_float2(acc[mi][nf][2] + b0, acc[mi][nf][3] + b1);
                *(float2*)(C + (size_t)(r0 + 8) * N + col) = v;
            }
        }
    }
}

// ---------------- elementwise split ------------------------------------------
__global__ __launch_bounds__(256)
void k_split(const float* __restrict__ s, bf16* __restrict__ h, bf16* __restrict__ l, int n)
{
    int i = blockIdx.x * 256 + threadIdx.x;
    int stride = gridDim.x * 256;
    for (; i < n; i += stride) bsplit(s[i], &h[i], &l[i]);
}

// ---------------- LayerNorm + SiLU -> bf16 split -----------------------------
__global__ __launch_bounds__(128)
void k_ln_silu(const float* __restrict__ pre, const float* __restrict__ gam,
               const float* __restrict__ bet)
{
    int e = blockIdx.x, t = threadIdx.x;
    float v = pre[(size_t)e * 128 + t];
    __shared__ float s1[4], s2[4];
    float a = v, a2 = v * v;
#pragma unroll
    for (int o = 16; o > 0; o >>= 1) {
        a  += __shfl_xor_sync(0xffffffffu, a,  o);
        a2 += __shfl_xor_sync(0xffffffffu, a2, o);
    }
    int w = t >> 5;
    if ((t & 31) == 0) { s1[w] = a; s2[w] = a2; }
    __syncthreads();
    float sum = s1[0] + s1[1] + s1[2] + s1[3];
    float sq  = s2[0] + s2[1] + s2[2] + s2[3];
    float mu  = sum * (1.f / 128.f);
    float var = sq * (1.f / 128.f) - mu * mu;
    if (var < 0.f) var = 0.f;
    float h = (v - mu) * rsqrtf(var + 1e-5f) * gam[t] + bet[t];
    float o = h / (1.f + expf(-h));
    size_t idx = (size_t)e * 128 + t;
    bsplit(o, &g_h_h[idx], &g_h_l[idx]);
}

// ---------------- rotation 1: gather + wigner + perm + rad-scale -> splits ---
__global__ __launch_bounds__(256)
void k_rot1(const float* __restrict__ x, const float* __restrict__ wigner,
            const int* __restrict__ edge_index)
{
    int e = blockIdx.x;
    int c = threadIdx.x;
    __shared__ float wg[19][25];

    for (int t = c; t < 19 * 25; t += 256) {
        int k = t / 25, j = t - k * 25;
        int om = k + (k >= 9 ? 1 : 0) + (k >= 14 ? 3 : 0);
        wg[k][j] = wigner[(size_t)e * 625 + om * 25 + j];
    }

    int src = edge_index[e];
    int dst = edge_index[NE + e];
    const float* xp = x + (size_t)(c < 128 ? src : dst) * 3200 + (c & 127);
    float xr[25];
#pragma unroll
    for (int j = 0; j < 25; j++) xr[j] = xp[j * 128];
    __syncthreads();

    const float* radp = g_rad + (size_t)e * 3072;
    const int PERM_[19] = {0,2,6,11,16, 3,7,12,17, 1,5,10,15, 8,13,18, 4,9,14};

#pragma unroll
    for (int p = 0; p < 19; p++) {
        int k = PERM_[p];
        float acc = 0.f;
#pragma unroll
        for (int j = 0; j < 25; j++) acc += wg[k][j] * xr[j];

        if (p < 5) {
            float v = acc * radp[p * 256 + c];
            size_t i = (size_t)e * 1280 + p * 256 + c;
            bsplit(v, &g_x0_h[i], &g_x0_l[i]);
        } else if (p < 13) {
            int s = (p - 5) & 3, rr = (p - 5) >> 2;
            float v = acc * radp[1280 + s * 256 + c];
            size_t i = ((size_t)e * 2 + rr) * 1024 + s * 256 + c;
            bsplit(v, &g_x1_h[i], &g_x1_l[i]);
        } else {
            int s = (p - 13) % 3, rr = (p - 13) / 3;
            float v = acc * radp[2304 + s * 256 + c];
            size_t i = ((size_t)e * 2 + rr) * 768 + s * 256 + c;
            bsplit(v, &g_x2_h[i], &g_x2_l[i]);
        }
    }
}

// ---------------- assemble conv1 out + gating -> conv2 inputs (splits) -------
__global__ __launch_bounds__(128)
void k_assemble1()
{
    int e = blockIdx.x, c = threadIdx.x;
    const float* c0 = g_c0 + (size_t)e * 1152;

    float gate[4];
#pragma unroll
    for (int l = 0; l < 4; l++) gate[l] = 1.f / (1.f + expf(-c0[l * 128 + c]));

#pragma unroll
    for (int p = 0; p < 5; p++) {
        float v = c0[512 + p * 128 + c];
        if (p == 0) v = v / (1.f + expf(-v));
        else        v *= gate[p - 1];
        size_t i = (size_t)e * 640 + p * 128 + c;
        bsplit(v, &g_u0_h[i], &g_u0_l[i]);
    }

    const float* c1a = g_c1 + (size_t)e * 2048;
    const float* c1b = c1a + 1024;
#pragma unroll
    for (int s = 0; s < 4; s++) {
        float yr0 = c1a[s * 128 + c], yi0 = c1a[512 + s * 128 + c];
        float yr1 = c1b[s * 128 + c], yi1 = c1b[512 + s * 128 + c];
        size_t i0 = ((size_t)e * 2 + 0) * 512 + s * 128 + c;
        size_t i1 = ((size_t)e * 2 + 1) * 512 + s * 128 + c;
        bsplit((yr0 - yi1) * gate[s], &g_u1_h[i0], &g_u1_l[i0]);
        bsplit((yr1 + yi0) * gate[s], &g_u1_h[i1], &g_u1_l[i1]);
    }

    const float* c2a = g_c2 + (size_t)e * 1536;
    const float* c2b = c2a + 768;
#pragma unroll
    for (int s = 0; s < 3; s++) {
        float yr0 = c2a[s * 128 + c], yi0 = c2a[384 + s * 128 + c];
        float yr1 = c2b[s * 128 + c], yi1 = c2b[384 + s * 128 + c];
        size_t i0 = ((size_t)e * 2 + 0) * 384 + s * 128 + c;
        size_t i1 = ((size_t)e * 2 + 1) * 384 + s * 128 + c;
        bsplit((yr0 - yi1) * gate[s + 1], &g_u2_h[i0], &g_u2_l[i0]);
        bsplit((yr1 + yi0) * gate[s + 1], &g_u2_h[i1], &g_u2_l[i1]);
    }
}

// ---------------- rotation 2: combine + envelope + wigner_inv + scatter ------
__global__ __launch_bounds__(128)
void k_rot2(const float* __restrict__ wigner_inv, const float* __restrict__ edist,
            const int* __restrict__ edge_index, const int* __restrict__ node_off,
            float* __restrict__ out)
{
    int e = blockIdx.x, c = threadIdx.x;
    __shared__ float wi[625];
    __shared__ float msg[19][128];

    for (int t = c; t < 625; t += 128) wi[t] = wigner_inv[(size_t)e * 625 + t];

    float d = edist[e] * (1.f / 6.f);
    float env = 0.f;
    if (d < 1.f) {
        float d2 = d * d, d4 = d2 * d2, d5 = d4 * d;
        env = 1.f + d5 * (-21.f + d * (35.f - 15.f * d));
    }

    const float* d0  = g_d0 + (size_t)e * 640;
    const float* d1a = g_d1 + (size_t)e * 2048; const float* d1b = d1a + 1024;
    const float* d2a = g_d2 + (size_t)e * 1536; const float* d2b = d2a + 768;
    const int PERM_[19] = {0,2,6,11,16, 3,7,12,17, 1,5,10,15, 8,13,18, 4,9,14};

#pragma unroll
    for (int p = 0; p < 19; p++) {
        float v;
        if (p < 5) {
            v = d0[p * 128 + c];
        } else if (p < 13) {
            int s = (p - 5) & 3, rr = (p - 5) >> 2;
            v = (rr == 0) ? d1a[s * 128 + c] - d1b[512 + s * 128 + c]
                          : d1b[s * 128 + c] + d1a[512 + s * 128 + c];
        } else {
            int s = (p - 13) % 3, rr = (p - 13) / 3;
            v = (rr == 0) ? d2a[s * 128 + c] - d2b[384 + s * 128 + c]
                          : d2b[s * 128 + c] + d2a[384 + s * 128 + c];
        }
        msg[PERM_[p]][c] = v * env;
    }
    __syncthreads();

    int nd = edge_index[NE + e] - node_off[0];
    float* op = out + (size_t)nd * 3200 + c;
#pragma unroll
    for (int i = 0; i < 25; i++) {
        float acc = 0.f;
#pragma unroll
        for (int k = 0; k < 19; k++) {
            int om = k + (k >= 9 ? 1 : 0) + (k >= 14 ? 3 : 0);
            acc += wi[i * 25 + om] * msg[k][c];
        }
        atomicAdd(op + i * 128, acc);
    }
}

// ---------------- host launch -------------------------------------------------
extern "C" void kernel_launch(void* const* d_in, const int* in_sizes, int n_in,
                              void* d_out, int out_size)
{
    const float* x          = (const float*)d_in[0];
    const float* x_edge     = (const float*)d_in[1];
    const float* edist      = (const float*)d_in[2];
    const float* wigner     = (const float*)d_in[3];
    const float* wigner_inv = (const float*)d_in[4];
    const float* W_r1       = (const float*)d_in[5];
    const float* b_r1       = (const float*)d_in[6];
    const float* ln_g       = (const float*)d_in[7];
    const float* ln_b       = (const float*)d_in[8];
    const float* W_r2       = (const float*)d_in[9];
    const float* b_r2       = (const float*)d_in[10];
    const float* W0_1       = (const float*)d_in[11];
    const float* b0_1       = (const float*)d_in[12];
    const float* Wm1_1      = (const float*)d_in[13];
    const float* Wm2_1      = (const float*)d_in[14];
    const float* W0_2       = (const float*)d_in[15];
    const float* b0_2       = (const float*)d_in[16];
    const float* Wm1_2      = (const float*)d_in[17];
    const float* Wm2_2      = (const float*)d_in[18];
    const int*   eidx       = (const int*)d_in[19];
    const int*   noff       = (const int*)d_in[20];
    float*       out        = (float*)d_out;

    cudaFuncSetAttribute(tcgemm, cudaFuncAttributeMaxDynamicSharedMemorySize, SMEM_SZ);

    float *pre, *rad, *c0, *c1, *c2, *dd0, *dd1, *dd2;
    bf16 *xeh, *xel, *hh, *hl, *x0h, *x0l, *x1h, *x1l, *x2h, *x2l;
    bf16 *u0h, *u0l, *u1h, *u1l, *u2h, *u2l, *wh, *wl;
    cudaGetSymbolAddress((void**)&pre, g_pre);
    cudaGetSymbolAddress((void**)&rad, g_rad);
    cudaGetSymbolAddress((void**)&c0,  g_c0);
    cudaGetSymbolAddress((void**)&c1,  g_c1);
    cudaGetSymbolAddress((void**)&c2,  g_c2);
    cudaGetSymbolAddress((void**)&dd0, g_d0);
    cudaGetSymbolAddress((void**)&dd1, g_d1);
    cudaGetSymbolAddress((void**)&dd2, g_d2);
    cudaGetSymbolAddress((void**)&xeh, g_xe_h); cudaGetSymbolAddress((void**)&xel, g_xe_l);
    cudaGetSymbolAddress((void**)&hh,  g_h_h);  cudaGetSymbolAddress((void**)&hl,  g_h_l);
    cudaGetSymbolAddress((void**)&x0h, g_x0_h); cudaGetSymbolAddress((void**)&x0l, g_x0_l);
    cudaGetSymbolAddress((void**)&x1h, g_x1_h); cudaGetSymbolAddress((void**)&x1l, g_x1_l);
    cudaGetSymbolAddress((void**)&x2h, g_x2_h); cudaGetSymbolAddress((void**)&x2l, g_x2_l);
    cudaGetSymbolAddress((void**)&u0h, g_u0_h); cudaGetSymbolAddress((void**)&u0l, g_u0_l);
    cudaGetSymbolAddress((void**)&u1h, g_u1_h); cudaGetSymbolAddress((void**)&u1l, g_u1_l);
    cudaGetSymbolAddress((void**)&u2h, g_u2_h); cudaGetSymbolAddress((void**)&u2l, g_u2_l);
    cudaGetSymbolAddress((void**)&wh,  g_w_h);  cudaGetSymbolAddress((void**)&wl,  g_w_l);

    // weight + input splits
    k_split<<<64,  256>>>(W_r1,  wh + W_R1,  wl + W_R1,  16384);
    k_split<<<128, 256>>>(W_r2,  wh + W_R2,  wl + W_R2,  393216);
    k_split<<<256, 256>>>(W0_1,  wh + W_01,  wl + W_01,  1474560);
    k_split<<<256, 256>>>(Wm1_1, wh + W_M11, wl + W_M11, 1048576);
    k_split<<<256, 256>>>(Wm2_1, wh + W_M21, wl + W_M21, 589824);
    k_split<<<256, 256>>>(W0_2,  wh + W_02,  wl + W_02,  409600);
    k_split<<<256, 256>>>(Wm1_2, wh + W_M12, wl + W_M12, 524288);
    k_split<<<256, 256>>>(Wm2_2, wh + W_M22, wl + W_M22, 294912);
    k_split<<<512, 256>>>(x_edge, xeh, xel, NE * 128);

    const int gy1 = (NE + 127) / 128;            // 391
    const int gy2 = (2 * NE + 127) / 128;        // 782

    // radial MLP
    tcgemm<<<dim3(1, gy1), 256, SMEM_SZ>>>(xeh, xel, wh + W_R1, wl + W_R1, b_r1, pre, NE, 128, 128);
    k_ln_silu<<<NE, 128>>>(pre, ln_g, ln_b);
    tcgemm<<<dim3(24, gy1), 256, SMEM_SZ>>>(hh, hl, wh + W_R2, wl + W_R2, b_r2, rad, NE, 3072, 128);

    // gather + wigner rotation + rad scaling (writes bf16 splits)
    k_rot1<<<NE, 256>>>(x, wigner, eidx);

    // SO2 conv 1
    tcgemm<<<dim3(9, gy1), 256, SMEM_SZ>>>(x0h, x0l, wh + W_01,  wl + W_01,  b0_1,    c0, NE,     1152, 1280);
    tcgemm<<<dim3(8, gy2), 256, SMEM_SZ>>>(x1h, x1l, wh + W_M11, wl + W_M11, nullptr, c1, 2 * NE, 1024, 1024);
    tcgemm<<<dim3(6, gy2), 256, SMEM_SZ>>>(x2h, x2l, wh + W_M21, wl + W_M21, nullptr, c2, 2 * NE, 768,  768);

    // gating / assembly (writes bf16 splits)
    k_assemble1<<<NE, 128>>>();

    // SO2 conv 2
    tcgemm<<<dim3(5, gy1), 256, SMEM_SZ>>>(u0h, u0l, wh + W_02,  wl + W_02,  b0_2,    dd0, NE,     640,  640);
    tcgemm<<<dim3(8, gy2), 256, SMEM_SZ>>>(u1h, u1l, wh + W_M12, wl + W_M12, nullptr, dd1, 2 * NE, 1024, 512);
    tcgemm<<<dim3(6, gy2), 256, SMEM_SZ>>>(u2h, u2l, wh + W_M22, wl + W_M22, nullptr, dd2, 2 * NE, 768,  384);

    // inverse rotation + envelope + scatter-add
    cudaMemsetAsync(d_out, 0, (size_t)out_size * sizeof(float), 0);
    k_rot2<<<NE, 128>>>(wigner_inv, edist, eidx, noff, out);
}